// round 1
// baseline (speedup 1.0000x reference)
#include <cuda_runtime.h>
#include <cuda_bf16.h>

#define NNODE 50000
#define EDGES 600000
#define NGRAPH 500
#define NPG 100
#define KSEL 30
#define FIN 128
#define D 64
#define DT 129

// ---------------- scratch (static device memory; no allocations) ----------------
__device__ float g_dinv[NNODE];
__device__ int   g_cnt[NNODE];
__device__ int   g_off[NNODE + 1];
__device__ int   g_bsum[64];
__device__ int   g_csrc[EDGES];
__device__ float g_H[NNODE * D];      // pre-aggregation features (X @ W)
__device__ float g_h[NNODE * D];      // post-aggregation activations (relu'd)
__device__ float g_s0[NNODE];
__device__ float g_s1[NNODE];
__device__ float g_u[NNODE];
__device__ float g_h3[NNODE];
__device__ float g_feats[NNODE * DT];

// ---------------- graph setup: degree, CSR-by-dst ----------------
__global__ void k_zero_cnt() {
    int i = blockIdx.x * blockDim.x + threadIdx.x;
    if (i < NNODE) g_cnt[i] = 0;
}

__global__ void k_count(const int* __restrict__ ei) {
    int e = blockIdx.x * blockDim.x + threadIdx.x;
    if (e >= EDGES) return;
    atomicAdd(&g_cnt[ei[EDGES + e]], 1);
}

// two-level exclusive scan of g_cnt -> g_off
__global__ void k_scan1() {
    __shared__ int sm[1024];
    int tx = threadIdx.x;
    int i = blockIdx.x * 1024 + tx;
    int v = (i < NNODE) ? g_cnt[i] : 0;
    sm[tx] = v;
    __syncthreads();
    for (int d = 1; d < 1024; d <<= 1) {
        int t = (tx >= d) ? sm[tx - d] : 0;
        __syncthreads();
        sm[tx] += t;
        __syncthreads();
    }
    if (i < NNODE) g_off[i] = sm[tx] - v;   // block-local exclusive
    if (tx == 1023) g_bsum[blockIdx.x] = sm[1023];
}

__global__ void k_scan2(int nblocks) {
    if (threadIdx.x == 0 && blockIdx.x == 0) {
        int run = 0;
        for (int b = 0; b < nblocks; b++) {
            int t = g_bsum[b];
            g_bsum[b] = run;
            run += t;
        }
    }
}

__global__ void k_scan3() {
    int i = blockIdx.x * blockDim.x + threadIdx.x;
    if (i < NNODE) g_off[i] += g_bsum[i >> 10];
    if (i == 0) g_off[NNODE] = EDGES;
}

__global__ void k_dinv() {
    int i = blockIdx.x * blockDim.x + threadIdx.x;
    if (i >= NNODE) return;
    g_dinv[i] = rsqrtf((float)g_cnt[i] + 1.0f);  // +1 self-loop
    g_cnt[i] = 0;                                 // reuse as fill cursor
}

__global__ void k_fill(const int* __restrict__ ei) {
    int e = blockIdx.x * blockDim.x + threadIdx.x;
    if (e >= EDGES) return;
    int s = ei[e];
    int d = ei[EDGES + e];
    int p = atomicAdd(&g_cnt[d], 1);
    g_csrc[g_off[d] + p] = s;
}

// ---------------- GEMM: out[N,64] = X[N,KD] @ W[KD,64] ----------------
template <int KD>
__global__ void k_gemm64(const float* __restrict__ X, const float* __restrict__ W,
                         float* __restrict__ out) {
    __shared__ float Ws[KD * 64];
    __shared__ float Xs[16 * KD];
    int tid = threadIdx.x;  // 256
    for (int idx = tid; idx < KD * 64; idx += 256) Ws[idx] = W[idx];
    int rb = blockIdx.x * 16;
    for (int idx = tid; idx < 16 * KD; idx += 256) Xs[idx] = X[rb * KD + idx];
    __syncthreads();
    int c = tid & 63;
    int r0 = tid >> 6;  // 0..3
    float a0 = 0.f, a1 = 0.f, a2 = 0.f, a3 = 0.f;
#pragma unroll 8
    for (int k = 0; k < KD; k++) {
        float wv = Ws[k * 64 + c];
        a0 += Xs[(r0     ) * KD + k] * wv;
        a1 += Xs[(r0 +  4) * KD + k] * wv;
        a2 += Xs[(r0 +  8) * KD + k] * wv;
        a3 += Xs[(r0 + 12) * KD + k] * wv;
    }
    out[(rb + r0     ) * 64 + c] = a0;
    out[(rb + r0 +  4) * 64 + c] = a1;
    out[(rb + r0 +  8) * 64 + c] = a2;
    out[(rb + r0 + 12) * 64 + c] = a3;
}

// ---------------- 64-wide GCN aggregation (one warp per node) ----------------
__global__ void k_agg64(const float* __restrict__ Hin, const float* __restrict__ bias,
                        float* __restrict__ out, int relu) {
    int warp = (blockIdx.x * blockDim.x + threadIdx.x) >> 5;
    int lane = threadIdx.x & 31;
    if (warp >= NNODE) return;
    int i = warp;
    float di = g_dinv[i];
    float a0 = bias[lane]      + Hin[i * 64 + lane]      * di * di;
    float a1 = bias[lane + 32] + Hin[i * 64 + lane + 32] * di * di;
    int e0 = g_off[i], e1 = g_off[i + 1];
    for (int j = e0; j < e1; j++) {
        int s = g_csrc[j];
        float w = g_dinv[s] * di;
        a0 += Hin[s * 64 + lane]      * w;
        a1 += Hin[s * 64 + lane + 32] * w;
    }
    if (relu) { a0 = fmaxf(a0, 0.f); a1 = fmaxf(a1, 0.f); }
    out[i * 64 + lane]      = a0;
    out[i * 64 + lane + 32] = a1;
}

// ---------------- per-node dot: out[i] = h[i,:] . w ----------------
__global__ void k_dot64(const float* __restrict__ Hm, const float* __restrict__ w,
                        float* __restrict__ out) {
    int warp = (blockIdx.x * blockDim.x + threadIdx.x) >> 5;
    int lane = threadIdx.x & 31;
    if (warp >= NNODE) return;
    float v = Hm[warp * 64 + lane] * w[lane] + Hm[warp * 64 + 32 + lane] * w[32 + lane];
#pragma unroll
    for (int o = 16; o; o >>= 1) v += __shfl_xor_sync(0xffffffffu, v, o);
    if (lane == 0) out[warp] = v;
}

// ---------------- scalar (1-wide) GCN aggregation ----------------
__global__ void k_aggscalar(const float* __restrict__ t, const float* __restrict__ bias,
                            const float* __restrict__ scale, float* __restrict__ out, int relu) {
    int i = blockIdx.x * blockDim.x + threadIdx.x;
    if (i >= NNODE) return;
    float di = g_dinv[i];
    float acc = t[i] * di * di;
    int e0 = g_off[i], e1 = g_off[i + 1];
    for (int j = e0; j < e1; j++) {
        int s = g_csrc[j];
        acc += t[s] * g_dinv[s] * di;
    }
    float sc = scale ? scale[0] : 1.0f;
    acc = acc * sc + bias[0];
    if (relu) acc = fmaxf(acc, 0.f);
    out[i] = acc;
}

// ---------------- gate multiply into feats columns ----------------
__global__ void k_mulstore(const float* __restrict__ s, const float* __restrict__ h, int base) {
    int idx = blockIdx.x * blockDim.x + threadIdx.x;
    if (idx >= NNODE * 64) return;
    int i = idx >> 6, c = idx & 63;
    g_feats[i * DT + base + c] = s[i] * h[idx];
}

__global__ void k_x3() {
    int i = blockIdx.x * blockDim.x + threadIdx.x;
    if (i >= NNODE) return;
    g_feats[i * DT + 128] = g_s1[i] * g_h3[i];
}

// ---------------- fused sort-pool + conv head (one block per graph) ----------------
__global__ void k_head(const float* __restrict__ Wc1, const float* __restrict__ bc1,
                       const float* __restrict__ Wc2, const float* __restrict__ bc2,
                       const float* __restrict__ Wl1, const float* __restrict__ bl1,
                       const float* __restrict__ Wl2, const float* __restrict__ bl2,
                       float* __restrict__ out) {
    __shared__ unsigned long long keys[NPG];
    __shared__ int sel[KSEL];
    __shared__ float pooled[KSEL * DT];
    __shared__ float c1s[16 * 30];
    __shared__ float mps[16 * 15];
    __shared__ float flat[32 * 11];
    __shared__ float red[128];
    int g = blockIdx.x, tid = threadIdx.x;
    int base = g * NPG;

    // keys: total-order encode of (-x3), tie-broken by node index (matches stable argsort)
    for (int i = tid; i < NPG; i += 128) {
        float x3v = g_feats[(base + i) * DT + 128];
        unsigned u = __float_as_uint(-x3v);
        u = (u & 0x80000000u) ? ~u : (u | 0x80000000u);
        keys[i] = ((unsigned long long)u << 32) | (unsigned)i;
    }
    __syncthreads();
    if (tid < NPG) {
        unsigned long long ki = keys[tid];
        int c = 0;
        for (int j = 0; j < NPG; j++) c += (keys[j] < ki) ? 1 : 0;
        if (c < KSEL) sel[c] = tid;
    }
    __syncthreads();
    // gather pooled [30,129]
    for (int idx = tid; idx < KSEL * DT; idx += 128) {
        int r = idx / DT, d = idx - r * DT;
        pooled[idx] = g_feats[(base + sel[r]) * DT + d];
    }
    __syncthreads();
    // conv1d(1->16, k=129, stride=129) + relu
    for (int idx = tid; idx < 16 * 30; idx += 128) {
        int o = idx / 30, k = idx - o * 30;
        float acc = bc1[o];
        const float* w = Wc1 + o * DT;
        for (int d = 0; d < DT; d++) acc += pooled[k * DT + d] * w[d];
        c1s[o * 30 + k] = fmaxf(acc, 0.f);
    }
    __syncthreads();
    // maxpool(2,2)
    for (int idx = tid; idx < 16 * 15; idx += 128) {
        int o = idx / 15, p = idx - o * 15;
        mps[idx] = fmaxf(c1s[o * 30 + 2 * p], c1s[o * 30 + 2 * p + 1]);
    }
    __syncthreads();
    // conv1d(16->32, k=5) + relu ; flat layout [o*11+p]
    for (int idx = tid; idx < 32 * 11; idx += 128) {
        int o = idx / 11, p = idx - o * 11;
        float acc = bc2[o];
        for (int i2 = 0; i2 < 16; i2++) {
            const float* w = Wc2 + (o * 16 + i2) * 5;
#pragma unroll
            for (int t = 0; t < 5; t++) acc += mps[i2 * 15 + p + t] * w[t];
        }
        flat[idx] = fmaxf(acc, 0.f);
    }
    __syncthreads();
    // FC 352->128 (relu) then dot with Wl2
    {
        int j = tid;  // exactly 128 threads
        float acc = bl1[j];
        const float* w = Wl1 + j * 352;
        for (int q = 0; q < 352; q++) acc += flat[q] * w[q];
        float hv = fmaxf(acc, 0.f);
        red[j] = hv * Wl2[j];
    }
    __syncthreads();
    for (int off = 64; off; off >>= 1) {
        if (tid < off) red[tid] += red[tid + off];
        __syncthreads();
    }
    if (tid == 0) out[g] = red[0] + bl2[0];
}

// ---------------- launcher ----------------
extern "C" void kernel_launch(void* const* d_in, const int* in_sizes, int n_in,
                              void* d_out, int out_size) {
    const float* x   = (const float*)d_in[0];
    const int*   ei  = (const int*)  d_in[1];
    const float* W1  = (const float*)d_in[2];
    const float* b1  = (const float*)d_in[3];
    const float* W2  = (const float*)d_in[4];
    const float* b2  = (const float*)d_in[5];
    const float* W3  = (const float*)d_in[6];
    const float* b3  = (const float*)d_in[7];
    const float* Ws1 = (const float*)d_in[8];
    const float* bs1 = (const float*)d_in[9];
    const float* Ws2 = (const float*)d_in[10];
    const float* bs2 = (const float*)d_in[11];
    const float* Ws3 = (const float*)d_in[12];
    const float* bs3 = (const float*)d_in[13];
    const float* Wc1 = (const float*)d_in[14];
    const float* bc1 = (const float*)d_in[15];
    const float* Wc2 = (const float*)d_in[16];
    const float* bc2 = (const float*)d_in[17];
    const float* Wl1 = (const float*)d_in[18];
    const float* bl1 = (const float*)d_in[19];
    const float* Wl2 = (const float*)d_in[20];
    const float* bl2 = (const float*)d_in[21];
    float* out = (float*)d_out;

    float *dH, *dh, *ds0, *ds1, *du, *dh3;
    cudaGetSymbolAddress((void**)&dH,  g_H);
    cudaGetSymbolAddress((void**)&dh,  g_h);
    cudaGetSymbolAddress((void**)&ds0, g_s0);
    cudaGetSymbolAddress((void**)&ds1, g_s1);
    cudaGetSymbolAddress((void**)&du,  g_u);
    cudaGetSymbolAddress((void**)&dh3, g_h3);

    const int TB = 256;
    int gN  = (NNODE + TB - 1) / TB;
    int gE  = (EDGES + TB - 1) / TB;
    int gW  = (NNODE * 32 + TB - 1) / TB;   // warp-per-node kernels
    int gM  = (NNODE * 64 + TB - 1) / TB;
    int nScanBlocks = (NNODE + 1023) / 1024;

    // --- graph structure ---
    k_zero_cnt<<<gN, TB>>>();
    k_count<<<gE, TB>>>(ei);
    k_scan1<<<nScanBlocks, 1024>>>();
    k_scan2<<<1, 32>>>(nScanBlocks);
    k_scan3<<<gN, TB>>>();
    k_dinv<<<gN, TB>>>();
    k_fill<<<gE, TB>>>(ei);

    // --- layer 1 ---
    k_gemm64<FIN><<<NNODE / 16, 256>>>(x, W1, dH);
    k_agg64<<<gW, TB>>>(dH, b1, dh, 1);                 // h1 (relu) in g_h
    // gate x1
    k_dot64<<<gW, TB>>>(dh, Ws1, ds0);
    k_aggscalar<<<gN, TB>>>(ds0, bs1, nullptr, ds1, 0);
    k_mulstore<<<gM, TB>>>(ds1, dh, 0);                 // feats[:,0:64]

    // --- layer 2 ---
    k_gemm64<D><<<NNODE / 16, 256>>>(dh, W2, dH);
    k_agg64<<<gW, TB>>>(dH, b2, dh, 1);                 // h2 (relu) in g_h
    // gate x2
    k_dot64<<<gW, TB>>>(dh, Ws2, ds0);
    k_aggscalar<<<gN, TB>>>(ds0, bs2, nullptr, ds1, 0);
    k_mulstore<<<gM, TB>>>(ds1, dh, 64);                // feats[:,64:128]

    // --- layer 3 (1-wide) ---
    k_dot64<<<gW, TB>>>(dh, W3, du);
    k_aggscalar<<<gN, TB>>>(du, b3, nullptr, dh3, 1);   // h3 = relu(gcn)
    k_aggscalar<<<gN, TB>>>(dh3, bs3, Ws3, ds1, 0);     // s3 = gcn(h3*ws3)+bs3
    k_x3<<<gN, TB>>>();                                 // feats[:,128] = s3*h3

    // --- sort-pool + head ---
    k_head<<<NGRAPH, 128>>>(Wc1, bc1, Wc2, bc2, Wl1, bl1, Wl2, bl2, out);

    (void)in_sizes; (void)n_in; (void)out_size;
}

// round 2
// speedup vs baseline: 1.2577x; 1.2577x over previous
#include <cuda_runtime.h>
#include <cuda_bf16.h>

#define NNODE 50000
#define EDGES 600000
#define NGRAPH 500
#define NPG 100
#define KSEL 30
#define FIN 128
#define D 64
#define DT 129

// ---------------- scratch (static device memory) ----------------
__device__ float g_dinv[NNODE];
__device__ int   g_cnt[NNODE];          // zero-initialized; invariant: zero at call start
__device__ int   g_off[NNODE + 1];
__device__ int   g_csrc[EDGES];
__device__ float g_H[NNODE * D];        // pre-aggregation (X @ W)
__device__ float g_h[NNODE * D];        // post-aggregation activations
__device__ float g_s0[NNODE];
__device__ float g_u[NNODE];
__device__ float g_h3[NNODE];
__device__ float g_x1[NNODE * D];
__device__ float g_x2[NNODE * D];
__device__ float g_x3[NNODE];

// ---------------- setup ----------------
__global__ void k_count(const int* __restrict__ ei) {
    int e = blockIdx.x * blockDim.x + threadIdx.x;
    if (e >= EDGES) return;
    atomicAdd(&g_cnt[ei[EDGES + e]], 1);
}

// single-block scan: g_off (exclusive), g_dinv. 1024 threads.
__global__ void k_scan_dinv() {
    __shared__ int wsum[32];
    const int PER = 49;  // 1024*49 >= 50000
    int t = threadIdx.x;
    int base = t * PER;
    int local = 0;
    for (int k = 0; k < PER; k++) {
        int idx = base + k;
        if (idx < NNODE) local += g_cnt[idx];
    }
    int lane = t & 31, w = t >> 5;
    int v = local;
#pragma unroll
    for (int o = 1; o < 32; o <<= 1) {
        int n = __shfl_up_sync(0xffffffffu, v, o);
        if (lane >= o) v += n;
    }
    if (lane == 31) wsum[w] = v;
    __syncthreads();
    if (w == 0) {
        int s = wsum[lane];
#pragma unroll
        for (int o = 1; o < 32; o <<= 1) {
            int n = __shfl_up_sync(0xffffffffu, s, o);
            if (lane >= o) s += n;
        }
        wsum[lane] = s;
    }
    __syncthreads();
    int run = v - local + (w > 0 ? wsum[w - 1] : 0);
    for (int k = 0; k < PER; k++) {
        int idx = base + k;
        if (idx < NNODE) {
            int c = g_cnt[idx];
            g_off[idx] = run;
            run += c;
            g_dinv[idx] = rsqrtf((float)c + 1.0f);
        }
    }
    if (t == 1023) g_off[NNODE] = EDGES;
}

// fill CSR; atomicSub leaves g_cnt at zero for the next call
__global__ void k_fill(const int* __restrict__ ei) {
    int e = blockIdx.x * blockDim.x + threadIdx.x;
    if (e >= EDGES) return;
    int s = ei[e];
    int d = ei[EDGES + e];
    int p = atomicSub(&g_cnt[d], 1) - 1;
    g_csrc[g_off[d] + p] = s;
}

// ---------------- register-tiled SGEMM: out[N,64] = X[N,K] @ W[K,64] ----------------
template <int K>
__global__ void __launch_bounds__(256) k_gemm(const float* __restrict__ X,
                                              const float* __restrict__ W,
                                              float* __restrict__ out) {
    __shared__ float Xt[16][132];
    __shared__ float Wsm[16][64];
    int tid = threadIdx.x;
    int rb = blockIdx.x * 128;
    int tx = tid & 15, ty = tid >> 4;
    float acc[8][4] = {};
#pragma unroll 1
    for (int k0 = 0; k0 < K; k0 += 16) {
#pragma unroll
        for (int i = 0; i < 2; i++) {
            int idx = tid * 2 + i;
            int row = idx >> 2;
            int kk4 = idx & 3;
            float4 vv = make_float4(0.f, 0.f, 0.f, 0.f);
            int gr = rb + row;
            if (gr < NNODE) vv = *(const float4*)(X + (long)gr * K + k0 + kk4 * 4);
            Xt[kk4 * 4 + 0][row] = vv.x;
            Xt[kk4 * 4 + 1][row] = vv.y;
            Xt[kk4 * 4 + 2][row] = vv.z;
            Xt[kk4 * 4 + 3][row] = vv.w;
        }
        {
            int kk = tid >> 4;
            int c4 = tid & 15;
            *(float4*)&Wsm[kk][c4 * 4] = *(const float4*)(W + (k0 + kk) * 64 + c4 * 4);
        }
        __syncthreads();
#pragma unroll
        for (int kk = 0; kk < 16; kk++) {
            float a[8], b[4];
            *(float4*)&a[0] = *(const float4*)&Xt[kk][ty * 8];
            *(float4*)&a[4] = *(const float4*)&Xt[kk][ty * 8 + 4];
            *(float4*)&b[0] = *(const float4*)&Wsm[kk][tx * 4];
#pragma unroll
            for (int r = 0; r < 8; r++)
#pragma unroll
                for (int c = 0; c < 4; c++) acc[r][c] += a[r] * b[c];
        }
        __syncthreads();
    }
#pragma unroll
    for (int r = 0; r < 8; r++) {
        int gr = rb + ty * 8 + r;
        if (gr < NNODE) *(float4*)(out + (long)gr * 64 + tx * 4) =
            make_float4(acc[r][0], acc[r][1], acc[r][2], acc[r][3]);
    }
}

// ---------------- 64-wide GCN aggregation + fused dot products ----------------
// out = relu( norm-agg(Hin) + bias ); sg[i] = out[i,:].Wg ; su[i] = out[i,:].Wu (optional)
__global__ void k_agg64f(const float* __restrict__ Hin, const float* __restrict__ bias,
                         const float* __restrict__ Wg, const float* __restrict__ Wu,
                         float* __restrict__ out, float* __restrict__ sg,
                         float* __restrict__ su) {
    int warp = (blockIdx.x * blockDim.x + threadIdx.x) >> 5;
    int lane = threadIdx.x & 31;
    if (warp >= NNODE) return;
    int i = warp;
    float di = g_dinv[i];
    const float2* H2 = (const float2*)Hin;
    float2 self = H2[i * 32 + lane];
    float2 bv = ((const float2*)bias)[lane];
    float ax = bv.x + self.x * di * di;
    float ay = bv.y + self.y * di * di;
    int j = g_off[i], e1 = g_off[i + 1];
    for (; j + 1 < e1; j += 2) {
        int s0 = g_csrc[j], s1 = g_csrc[j + 1];
        float w0 = g_dinv[s0] * di, w1 = g_dinv[s1] * di;
        float2 v0 = H2[s0 * 32 + lane];
        float2 v1 = H2[s1 * 32 + lane];
        ax += v0.x * w0 + v1.x * w1;
        ay += v0.y * w0 + v1.y * w1;
    }
    if (j < e1) {
        int s = g_csrc[j];
        float w = g_dinv[s] * di;
        float2 v = H2[s * 32 + lane];
        ax += v.x * w;
        ay += v.y * w;
    }
    ax = fmaxf(ax, 0.f);
    ay = fmaxf(ay, 0.f);
    ((float2*)out)[i * 32 + lane] = make_float2(ax, ay);
    // fused dot(s)
    float2 wg = ((const float2*)Wg)[lane];
    float dg = ax * wg.x + ay * wg.y;
#pragma unroll
    for (int o = 16; o; o >>= 1) dg += __shfl_xor_sync(0xffffffffu, dg, o);
    if (lane == 0) sg[i] = dg;
    if (Wu) {
        float2 wu = ((const float2*)Wu)[lane];
        float du = ax * wu.x + ay * wu.y;
#pragma unroll
        for (int o = 16; o; o >>= 1) du += __shfl_xor_sync(0xffffffffu, du, o);
        if (lane == 0) su[i] = du;
    }
}

// ---------------- gate: s1 = norm-agg(s0) + bias ; dst[i,:] = s1 * h[i,:] ----------------
__global__ void k_gate(const float* __restrict__ s0, const float* __restrict__ h,
                       const float* __restrict__ bias, float* __restrict__ dst) {
    int warp = (blockIdx.x * blockDim.x + threadIdx.x) >> 5;
    int lane = threadIdx.x & 31;
    if (warp >= NNODE) return;
    int i = warp;
    float di = g_dinv[i];
    float acc = (lane == 0) ? s0[i] * di * di : 0.f;
    int e0 = g_off[i], e1 = g_off[i + 1];
    for (int j = e0 + lane; j < e1; j += 32) {
        int s = g_csrc[j];
        acc += s0[s] * g_dinv[s] * di;
    }
#pragma unroll
    for (int o = 16; o; o >>= 1) acc += __shfl_xor_sync(0xffffffffu, acc, o);
    float s1 = acc + bias[0];
    float2 hv = ((const float2*)h)[i * 32 + lane];
    ((float2*)dst)[i * 32 + lane] = make_float2(s1 * hv.x, s1 * hv.y);
}

// ---------------- layer-3 scalar kernels (warp per node) ----------------
__global__ void k_h3(const float* __restrict__ u, const float* __restrict__ b3) {
    int warp = (blockIdx.x * blockDim.x + threadIdx.x) >> 5;
    int lane = threadIdx.x & 31;
    if (warp >= NNODE) return;
    int i = warp;
    float di = g_dinv[i];
    float acc = (lane == 0) ? u[i] * di * di : 0.f;
    int e0 = g_off[i], e1 = g_off[i + 1];
    for (int j = e0 + lane; j < e1; j += 32) {
        int s = g_csrc[j];
        acc += u[s] * g_dinv[s] * di;
    }
#pragma unroll
    for (int o = 16; o; o >>= 1) acc += __shfl_xor_sync(0xffffffffu, acc, o);
    if (lane == 0) g_h3[i] = fmaxf(acc + b3[0], 0.f);
}

__global__ void k_s3(const float* __restrict__ Ws3, const float* __restrict__ bs3) {
    int warp = (blockIdx.x * blockDim.x + threadIdx.x) >> 5;
    int lane = threadIdx.x & 31;
    if (warp >= NNODE) return;
    int i = warp;
    float di = g_dinv[i];
    float hi = g_h3[i];
    float acc = (lane == 0) ? hi * di * di : 0.f;
    int e0 = g_off[i], e1 = g_off[i + 1];
    for (int j = e0 + lane; j < e1; j += 32) {
        int s = g_csrc[j];
        acc += g_h3[s] * g_dinv[s] * di;
    }
#pragma unroll
    for (int o = 16; o; o >>= 1) acc += __shfl_xor_sync(0xffffffffu, acc, o);
    if (lane == 0) g_x3[i] = (acc * Ws3[0] + bs3[0]) * hi;
}

// ---------------- fused sort-pool + conv head ----------------
__global__ void __launch_bounds__(128) k_head(
    const float* __restrict__ Wc1, const float* __restrict__ bc1,
    const float* __restrict__ Wc2, const float* __restrict__ bc2,
    const float* __restrict__ Wl1, const float* __restrict__ bl1,
    const float* __restrict__ Wl2, const float* __restrict__ bl2,
    float* __restrict__ out) {
    __shared__ unsigned long long keys[NPG];
    __shared__ int sel[KSEL];
    __shared__ float pooled[KSEL * DT];
    __shared__ float c1s[16 * 30];
    __shared__ float mps[16 * 15];
    __shared__ float flat[32 * 11];
    __shared__ float red[128];
    int g = blockIdx.x, tid = threadIdx.x;
    int base = g * NPG;

    // total-order key of (-x3), tie-broken by node index (stable argsort semantics)
    for (int i = tid; i < NPG; i += 128) {
        float x3v = g_x3[base + i];
        unsigned u = __float_as_uint(-x3v);
        u = (u & 0x80000000u) ? ~u : (u | 0x80000000u);
        keys[i] = ((unsigned long long)u << 32) | (unsigned)i;
    }
    __syncthreads();
    if (tid < NPG) {
        unsigned long long ki = keys[tid];
        int c = 0;
        for (int j = 0; j < NPG; j++) c += (keys[j] < ki) ? 1 : 0;
        if (c < KSEL) sel[c] = tid;
    }
    __syncthreads();
    // gather pooled [30,129]
    for (int idx = tid; idx < KSEL * DT; idx += 128) {
        int r = idx / DT, d = idx - r * DT;
        int node = base + sel[r];
        float v;
        if (d < 64) v = g_x1[node * 64 + d];
        else if (d < 128) v = g_x2[node * 64 + d - 64];
        else v = g_x3[node];
        pooled[idx] = v;
    }
    __syncthreads();
    // conv1d(1->16, k=129, stride=129) + relu
    for (int idx = tid; idx < 16 * 30; idx += 128) {
        int o = idx / 30, k = idx - o * 30;
        float acc = bc1[o];
        const float* w = Wc1 + o * DT;
        for (int d = 0; d < DT; d++) acc += pooled[k * DT + d] * w[d];
        c1s[o * 30 + k] = fmaxf(acc, 0.f);
    }
    __syncthreads();
    // maxpool(2,2)
    for (int idx = tid; idx < 16 * 15; idx += 128) {
        int o = idx / 15, p = idx - o * 15;
        mps[idx] = fmaxf(c1s[o * 30 + 2 * p], c1s[o * 30 + 2 * p + 1]);
    }
    __syncthreads();
    // conv1d(16->32, k=5) + relu
    for (int idx = tid; idx < 32 * 11; idx += 128) {
        int o = idx / 11, p = idx - o * 11;
        float acc = bc2[o];
        for (int i2 = 0; i2 < 16; i2++) {
            const float* w = Wc2 + (o * 16 + i2) * 5;
#pragma unroll
            for (int t = 0; t < 5; t++) acc += mps[i2 * 15 + p + t] * w[t];
        }
        flat[idx] = fmaxf(acc, 0.f);
    }
    __syncthreads();
    // FC 352->128 (relu) * Wl2 — coalesced: warp per 32 outputs, lanes stride q
    {
        int w = tid >> 5, lane = tid & 31;
        float fl[11];
#pragma unroll
        for (int it = 0; it < 11; it++) fl[it] = flat[lane + it * 32];
        for (int jj = 0; jj < 32; jj++) {
            int j = w * 32 + jj;
            const float* wr = Wl1 + j * 352;
            float acc = 0.f;
#pragma unroll
            for (int it = 0; it < 11; it++) acc += fl[it] * wr[lane + it * 32];
#pragma unroll
            for (int o = 16; o; o >>= 1) acc += __shfl_xor_sync(0xffffffffu, acc, o);
            if (lane == 0) {
                float hv = fmaxf(acc + bl1[j], 0.f);
                red[j] = hv * Wl2[j];
            }
        }
    }
    __syncthreads();
    for (int off = 64; off; off >>= 1) {
        if (tid < off) red[tid] += red[tid + off];
        __syncthreads();
    }
    if (tid == 0) out[g] = red[0] + bl2[0];
}

// ---------------- launcher ----------------
extern "C" void kernel_launch(void* const* d_in, const int* in_sizes, int n_in,
                              void* d_out, int out_size) {
    const float* x   = (const float*)d_in[0];
    const int*   ei  = (const int*)  d_in[1];
    const float* W1  = (const float*)d_in[2];
    const float* b1  = (const float*)d_in[3];
    const float* W2  = (const float*)d_in[4];
    const float* b2  = (const float*)d_in[5];
    const float* W3  = (const float*)d_in[6];
    const float* b3  = (const float*)d_in[7];
    const float* Ws1 = (const float*)d_in[8];
    const float* bs1 = (const float*)d_in[9];
    const float* Ws2 = (const float*)d_in[10];
    const float* bs2 = (const float*)d_in[11];
    const float* Ws3 = (const float*)d_in[12];
    const float* bs3 = (const float*)d_in[13];
    const float* Wc1 = (const float*)d_in[14];
    const float* bc1 = (const float*)d_in[15];
    const float* Wc2 = (const float*)d_in[16];
    const float* bc2 = (const float*)d_in[17];
    const float* Wl1 = (const float*)d_in[18];
    const float* bl1 = (const float*)d_in[19];
    const float* Wl2 = (const float*)d_in[20];
    const float* bl2 = (const float*)d_in[21];
    float* out = (float*)d_out;

    float *dH, *dh, *ds0, *du, *dx1, *dx2;
    cudaGetSymbolAddress((void**)&dH,  g_H);
    cudaGetSymbolAddress((void**)&dh,  g_h);
    cudaGetSymbolAddress((void**)&ds0, g_s0);
    cudaGetSymbolAddress((void**)&du,  g_u);
    cudaGetSymbolAddress((void**)&dx1, g_x1);
    cudaGetSymbolAddress((void**)&dx2, g_x2);

    const int TB = 256;
    int gE = (EDGES + TB - 1) / TB;
    int gW = (NNODE * 32 + TB - 1) / TB;

    // structure
    k_count<<<gE, TB>>>(ei);
    k_scan_dinv<<<1, 1024>>>();
    k_fill<<<gE, TB>>>(ei);

    // layer 1
    k_gemm<FIN><<<(NNODE + 127) / 128, 256>>>(x, W1, dH);
    k_agg64f<<<gW, TB>>>(dH, b1, Ws1, nullptr, dh, ds0, nullptr);
    k_gate<<<gW, TB>>>(ds0, dh, bs1, dx1);

    // layer 2 (fuse dot with W3 for layer 3)
    k_gemm<D><<<(NNODE + 127) / 128, 256>>>(dh, W2, dH);
    k_agg64f<<<gW, TB>>>(dH, b2, Ws2, W3, dh, ds0, du);
    k_gate<<<gW, TB>>>(ds0, dh, bs2, dx2);

    // layer 3
    k_h3<<<gW, TB>>>(du, b3);
    k_s3<<<gW, TB>>>(Ws3, bs3);

    // head
    k_head<<<NGRAPH, 128>>>(Wc1, bc1, Wc2, bc2, Wl1, bl1, Wl2, bl2, out);

    (void)in_sizes; (void)n_in; (void)out_size;
}

// round 3
// speedup vs baseline: 1.3379x; 1.0638x over previous
#include <cuda_runtime.h>
#include <cuda_bf16.h>

#define NNODE 50000
#define EDGES 600000
#define NGRAPH 500
#define NPG 100
#define KSEL 30
#define FIN 128
#define D 64
#define DT 129

// ---------------- scratch (static device memory) ----------------
__device__ float g_dinv[NNODE];
__device__ int   g_cnt[NNODE];          // zero-initialized; invariant: zero at call start
__device__ int   g_off[NNODE + 1];
__device__ int   g_csrc[EDGES];
__device__ float g_H[NNODE * D];
__device__ float g_h[NNODE * D];
__device__ float g_s0[NNODE];
__device__ float g_u[NNODE];
__device__ float g_h3[NNODE];
__device__ float g_x1[NNODE * D];
__device__ float g_x2[NNODE * D];
__device__ float g_x3[NNODE];

// ---------------- setup ----------------
__global__ void k_count(const int* __restrict__ ei) {
    int e = blockIdx.x * blockDim.x + threadIdx.x;
    if (e >= EDGES) return;
    atomicAdd(&g_cnt[ei[EDGES + e]], 1);
}

__global__ void k_scan_dinv() {
    __shared__ int wsum[32];
    const int PER = 49;
    int t = threadIdx.x;
    int base = t * PER;
    int local = 0;
    for (int k = 0; k < PER; k++) {
        int idx = base + k;
        if (idx < NNODE) local += g_cnt[idx];
    }
    int lane = t & 31, w = t >> 5;
    int v = local;
#pragma unroll
    for (int o = 1; o < 32; o <<= 1) {
        int n = __shfl_up_sync(0xffffffffu, v, o);
        if (lane >= o) v += n;
    }
    if (lane == 31) wsum[w] = v;
    __syncthreads();
    if (w == 0) {
        int s = wsum[lane];
#pragma unroll
        for (int o = 1; o < 32; o <<= 1) {
            int n = __shfl_up_sync(0xffffffffu, s, o);
            if (lane >= o) s += n;
        }
        wsum[lane] = s;
    }
    __syncthreads();
    int run = v - local + (w > 0 ? wsum[w - 1] : 0);
    for (int k = 0; k < PER; k++) {
        int idx = base + k;
        if (idx < NNODE) {
            int c = g_cnt[idx];
            g_off[idx] = run;
            run += c;
            g_dinv[idx] = rsqrtf((float)c + 1.0f);
        }
    }
    if (t == 1023) g_off[NNODE] = EDGES;
}

__global__ void k_fill(const int* __restrict__ ei) {
    int e = blockIdx.x * blockDim.x + threadIdx.x;
    if (e >= EDGES) return;
    int s = ei[e];
    int d = ei[EDGES + e];
    int p = atomicSub(&g_cnt[d], 1) - 1;
    g_csrc[g_off[d] + p] = s;
}

// ---------------- SGEMM: out[N,64] = X[N,K] @ W[K,64] ; 8x8 thread tile ----------------
template <int K>
__global__ void __launch_bounds__(128) k_gemm(const float* __restrict__ X,
                                              const float* __restrict__ W,
                                              float* __restrict__ out) {
    __shared__ float Xt[16][136];   // [kk][row], padded
    __shared__ float Wsm[16][64];
    int tid = threadIdx.x;          // 128
    int rb = blockIdx.x * 128;
    int tx = tid & 7;               // col group: cols tx*8 .. tx*8+7
    int ty = tid >> 3;              // row group: rows ty*8 .. ty*8+7
    float acc[8][8] = {};
#pragma unroll 1
    for (int k0 = 0; k0 < K; k0 += 16) {
        // load X tile: each thread loads its own row (row = tid), 4 float4s
        {
            int gr = rb + tid;
            float4 v0, v1, v2, v3;
            if (gr < NNODE) {
                const float4* xp = (const float4*)(X + (size_t)gr * K + k0);
                v0 = xp[0]; v1 = xp[1]; v2 = xp[2]; v3 = xp[3];
            } else {
                v0 = v1 = v2 = v3 = make_float4(0.f, 0.f, 0.f, 0.f);
            }
            Xt[0][tid] = v0.x;  Xt[1][tid] = v0.y;  Xt[2][tid] = v0.z;  Xt[3][tid] = v0.w;
            Xt[4][tid] = v1.x;  Xt[5][tid] = v1.y;  Xt[6][tid] = v1.z;  Xt[7][tid] = v1.w;
            Xt[8][tid] = v2.x;  Xt[9][tid] = v2.y;  Xt[10][tid] = v2.z; Xt[11][tid] = v2.w;
            Xt[12][tid] = v3.x; Xt[13][tid] = v3.y; Xt[14][tid] = v3.z; Xt[15][tid] = v3.w;
        }
        // load W tile: 16x64 = 256 float4, 2 per thread
#pragma unroll
        for (int i = 0; i < 2; i++) {
            int f = tid + i * 128;
            int kk = f >> 4, c4 = f & 15;
            *(float4*)&Wsm[kk][c4 * 4] = *(const float4*)(W + (size_t)(k0 + kk) * 64 + c4 * 4);
        }
        __syncthreads();
#pragma unroll
        for (int kk = 0; kk < 16; kk++) {
            float a[8], b[8];
            *(float4*)&a[0] = *(const float4*)&Xt[kk][ty * 8];
            *(float4*)&a[4] = *(const float4*)&Xt[kk][ty * 8 + 4];
            *(float4*)&b[0] = *(const float4*)&Wsm[kk][tx * 8];
            *(float4*)&b[4] = *(const float4*)&Wsm[kk][tx * 8 + 4];
#pragma unroll
            for (int r = 0; r < 8; r++)
#pragma unroll
                for (int c = 0; c < 8; c++) acc[r][c] += a[r] * b[c];
        }
        __syncthreads();
    }
#pragma unroll
    for (int r = 0; r < 8; r++) {
        int gr = rb + ty * 8 + r;
        if (gr < NNODE) {
            float4* op = (float4*)(out + (size_t)gr * 64 + tx * 8);
            op[0] = make_float4(acc[r][0], acc[r][1], acc[r][2], acc[r][3]);
            op[1] = make_float4(acc[r][4], acc[r][5], acc[r][6], acc[r][7]);
        }
    }
}

// ---------------- 64-wide GCN aggregation + fused dot products ----------------
__global__ void k_agg64f(const float* __restrict__ Hin, const float* __restrict__ bias,
                         const float* __restrict__ Wg, const float* __restrict__ Wu,
                         float* __restrict__ out, float* __restrict__ sg,
                         float* __restrict__ su) {
    int warp = (blockIdx.x * blockDim.x + threadIdx.x) >> 5;
    int lane = threadIdx.x & 31;
    if (warp >= NNODE) return;
    int i = warp;
    float di = g_dinv[i];
    const float2* H2 = (const float2*)Hin;
    float2 self = H2[i * 32 + lane];
    float2 bv = ((const float2*)bias)[lane];
    float ax = bv.x + self.x * di * di;
    float ay = bv.y + self.y * di * di;
    int j = g_off[i], e1 = g_off[i + 1];
    for (; j + 4 <= e1; j += 4) {
        int s0 = __ldg(&g_csrc[j]);
        int s1 = __ldg(&g_csrc[j + 1]);
        int s2 = __ldg(&g_csrc[j + 2]);
        int s3 = __ldg(&g_csrc[j + 3]);
        float w0 = g_dinv[s0] * di, w1 = g_dinv[s1] * di;
        float w2 = g_dinv[s2] * di, w3 = g_dinv[s3] * di;
        float2 v0 = H2[s0 * 32 + lane];
        float2 v1 = H2[s1 * 32 + lane];
        float2 v2 = H2[s2 * 32 + lane];
        float2 v3 = H2[s3 * 32 + lane];
        ax += v0.x * w0 + v1.x * w1 + v2.x * w2 + v3.x * w3;
        ay += v0.y * w0 + v1.y * w1 + v2.y * w2 + v3.y * w3;
    }
    for (; j < e1; j++) {
        int s = __ldg(&g_csrc[j]);
        float w = g_dinv[s] * di;
        float2 v = H2[s * 32 + lane];
        ax += v.x * w;
        ay += v.y * w;
    }
    ax = fmaxf(ax, 0.f);
    ay = fmaxf(ay, 0.f);
    ((float2*)out)[i * 32 + lane] = make_float2(ax, ay);
    float2 wg = ((const float2*)Wg)[lane];
    float dg = ax * wg.x + ay * wg.y;
#pragma unroll
    for (int o = 16; o; o >>= 1) dg += __shfl_xor_sync(0xffffffffu, dg, o);
    if (lane == 0) sg[i] = dg;
    if (Wu) {
        float2 wu = ((const float2*)Wu)[lane];
        float du = ax * wu.x + ay * wu.y;
#pragma unroll
        for (int o = 16; o; o >>= 1) du += __shfl_xor_sync(0xffffffffu, du, o);
        if (lane == 0) su[i] = du;
    }
}

// ---------------- gate (layer 1): 8 lanes per node ----------------
__global__ void k_gate(const float* __restrict__ s0, const float* __restrict__ h,
                       const float* __restrict__ bias, float* __restrict__ dst) {
    int gt = blockIdx.x * blockDim.x + threadIdx.x;
    int i = gt >> 3;
    int sub = threadIdx.x & 7;
    if (i >= NNODE) return;
    float di = g_dinv[i];
    float acc = (sub == 0) ? s0[i] * di * di : 0.f;
    int e0 = g_off[i], e1 = g_off[i + 1];
    for (int j = e0 + sub; j < e1; j += 8) {
        int s = __ldg(&g_csrc[j]);
        acc += s0[s] * g_dinv[s] * di;
    }
#pragma unroll
    for (int o = 4; o; o >>= 1) acc += __shfl_xor_sync(0xffffffffu, acc, o);
    float s1 = acc + bias[0];
    const float4* h4 = (const float4*)(h + (size_t)i * 64);
    float4* d4 = (float4*)(dst + (size_t)i * 64);
#pragma unroll
    for (int t = 0; t < 2; t++) {
        float4 v = h4[sub + t * 8];
        d4[sub + t * 8] = make_float4(s1 * v.x, s1 * v.y, s1 * v.z, s1 * v.w);
    }
}

// ---------------- gate (layer 2) + h3 fused: both scalar aggs over same edges ----------------
__global__ void k_gate2(const float* __restrict__ s0, const float* __restrict__ u,
                        const float* __restrict__ h,
                        const float* __restrict__ bs2, const float* __restrict__ b3,
                        float* __restrict__ dst) {
    int gt = blockIdx.x * blockDim.x + threadIdx.x;
    int i = gt >> 3;
    int sub = threadIdx.x & 7;
    if (i >= NNODE) return;
    float di = g_dinv[i];
    float accS = 0.f, accU = 0.f;
    if (sub == 0) { accS = s0[i] * di * di; accU = u[i] * di * di; }
    int e0 = g_off[i], e1 = g_off[i + 1];
    for (int j = e0 + sub; j < e1; j += 8) {
        int s = __ldg(&g_csrc[j]);
        float w = g_dinv[s] * di;
        accS += s0[s] * w;
        accU += u[s] * w;
    }
#pragma unroll
    for (int o = 4; o; o >>= 1) {
        accS += __shfl_xor_sync(0xffffffffu, accS, o);
        accU += __shfl_xor_sync(0xffffffffu, accU, o);
    }
    float s1 = accS + bs2[0];
    const float4* h4 = (const float4*)(h + (size_t)i * 64);
    float4* d4 = (float4*)(dst + (size_t)i * 64);
#pragma unroll
    for (int t = 0; t < 2; t++) {
        float4 v = h4[sub + t * 8];
        d4[sub + t * 8] = make_float4(s1 * v.x, s1 * v.y, s1 * v.z, s1 * v.w);
    }
    if (sub == 0) g_h3[i] = fmaxf(accU + b3[0], 0.f);
}

// ---------------- s3 / x3: 8 lanes per node ----------------
__global__ void k_s3(const float* __restrict__ Ws3, const float* __restrict__ bs3) {
    int gt = blockIdx.x * blockDim.x + threadIdx.x;
    int i = gt >> 3;
    int sub = threadIdx.x & 7;
    if (i >= NNODE) return;
    float di = g_dinv[i];
    float hi = g_h3[i];
    float acc = (sub == 0) ? hi * di * di : 0.f;
    int e0 = g_off[i], e1 = g_off[i + 1];
    for (int j = e0 + sub; j < e1; j += 8) {
        int s = __ldg(&g_csrc[j]);
        acc += g_h3[s] * g_dinv[s] * di;
    }
#pragma unroll
    for (int o = 4; o; o >>= 1) acc += __shfl_xor_sync(0xffffffffu, acc, o);
    if (sub == 0) g_x3[i] = (acc * Ws3[0] + bs3[0]) * hi;
}

// ---------------- fused sort-pool + conv head ----------------
__global__ void __launch_bounds__(128) k_head(
    const float* __restrict__ Wc1, const float* __restrict__ bc1,
    const float* __restrict__ Wc2, const float* __restrict__ bc2,
    const float* __restrict__ Wl1, const float* __restrict__ bl1,
    const float* __restrict__ Wl2, const float* __restrict__ bl2,
    float* __restrict__ out) {
    __shared__ unsigned long long keys[NPG];
    __shared__ int sel[KSEL];
    __shared__ float pooled[KSEL * DT];
    __shared__ float c1s[16 * 30];
    __shared__ float mps[16 * 15];
    __shared__ float flat[32 * 11];
    __shared__ float red[128];
    int g = blockIdx.x, tid = threadIdx.x;
    int base = g * NPG;

    for (int i = tid; i < NPG; i += 128) {
        float x3v = g_x3[base + i];
        unsigned u = __float_as_uint(-x3v);
        u = (u & 0x80000000u) ? ~u : (u | 0x80000000u);
        keys[i] = ((unsigned long long)u << 32) | (unsigned)i;
    }
    __syncthreads();
    if (tid < NPG) {
        unsigned long long ki = keys[tid];
        int c = 0;
        for (int j = 0; j < NPG; j++) c += (keys[j] < ki) ? 1 : 0;
        if (c < KSEL) sel[c] = tid;
    }
    __syncthreads();
    for (int idx = tid; idx < KSEL * DT; idx += 128) {
        int r = idx / DT, d = idx - r * DT;
        int node = base + sel[r];
        float v;
        if (d < 64) v = g_x1[node * 64 + d];
        else if (d < 128) v = g_x2[node * 64 + d - 64];
        else v = g_x3[node];
        pooled[idx] = v;
    }
    __syncthreads();
    for (int idx = tid; idx < 16 * 30; idx += 128) {
        int o = idx / 30, k = idx - o * 30;
        float acc = bc1[o];
        const float* w = Wc1 + o * DT;
        for (int d = 0; d < DT; d++) acc += pooled[k * DT + d] * w[d];
        c1s[o * 30 + k] = fmaxf(acc, 0.f);
    }
    __syncthreads();
    for (int idx = tid; idx < 16 * 15; idx += 128) {
        int o = idx / 15, p = idx - o * 15;
        mps[idx] = fmaxf(c1s[o * 30 + 2 * p], c1s[o * 30 + 2 * p + 1]);
    }
    __syncthreads();
    for (int idx = tid; idx < 32 * 11; idx += 128) {
        int o = idx / 11, p = idx - o * 11;
        float acc = bc2[o];
        for (int i2 = 0; i2 < 16; i2++) {
            const float* w = Wc2 + (o * 16 + i2) * 5;
#pragma unroll
            for (int t = 0; t < 5; t++) acc += mps[i2 * 15 + p + t] * w[t];
        }
        flat[idx] = fmaxf(acc, 0.f);
    }
    __syncthreads();
    {
        int w = tid >> 5, lane = tid & 31;
        float fl[11];
#pragma unroll
        for (int it = 0; it < 11; it++) fl[it] = flat[lane + it * 32];
        for (int jj = 0; jj < 32; jj++) {
            int j = w * 32 + jj;
            const float* wr = Wl1 + j * 352;
            float acc = 0.f;
#pragma unroll
            for (int it = 0; it < 11; it++) acc += fl[it] * wr[lane + it * 32];
#pragma unroll
            for (int o = 16; o; o >>= 1) acc += __shfl_xor_sync(0xffffffffu, acc, o);
            if (lane == 0) {
                float hv = fmaxf(acc + bl1[j], 0.f);
                red[j] = hv * Wl2[j];
            }
        }
    }
    __syncthreads();
    for (int off = 64; off; off >>= 1) {
        if (tid < off) red[tid] += red[tid + off];
        __syncthreads();
    }
    if (tid == 0) out[g] = red[0] + bl2[0];
}

// ---------------- launcher ----------------
extern "C" void kernel_launch(void* const* d_in, const int* in_sizes, int n_in,
                              void* d_out, int out_size) {
    const float* x   = (const float*)d_in[0];
    const int*   ei  = (const int*)  d_in[1];
    const float* W1  = (const float*)d_in[2];
    const float* b1  = (const float*)d_in[3];
    const float* W2  = (const float*)d_in[4];
    const float* b2  = (const float*)d_in[5];
    const float* W3  = (const float*)d_in[6];
    const float* b3  = (const float*)d_in[7];
    const float* Ws1 = (const float*)d_in[8];
    const float* bs1 = (const float*)d_in[9];
    const float* Ws2 = (const float*)d_in[10];
    const float* bs2 = (const float*)d_in[11];
    const float* Ws3 = (const float*)d_in[12];
    const float* bs3 = (const float*)d_in[13];
    const float* Wc1 = (const float*)d_in[14];
    const float* bc1 = (const float*)d_in[15];
    const float* Wc2 = (const float*)d_in[16];
    const float* bc2 = (const float*)d_in[17];
    const float* Wl1 = (const float*)d_in[18];
    const float* bl1 = (const float*)d_in[19];
    const float* Wl2 = (const float*)d_in[20];
    const float* bl2 = (const float*)d_in[21];
    float* out = (float*)d_out;

    float *dH, *dh, *ds0, *du, *dx1, *dx2;
    cudaGetSymbolAddress((void**)&dH,  g_H);
    cudaGetSymbolAddress((void**)&dh,  g_h);
    cudaGetSymbolAddress((void**)&ds0, g_s0);
    cudaGetSymbolAddress((void**)&du,  g_u);
    cudaGetSymbolAddress((void**)&dx1, g_x1);
    cudaGetSymbolAddress((void**)&dx2, g_x2);

    const int TB = 256;
    int gE  = (EDGES + TB - 1) / TB;
    int gW  = (NNODE * 32 + TB - 1) / TB;   // warp per node
    int gW8 = (NNODE * 8 + TB - 1) / TB;    // 8 lanes per node

    // structure
    k_count<<<gE, TB>>>(ei);
    k_scan_dinv<<<1, 1024>>>();
    k_fill<<<gE, TB>>>(ei);

    // layer 1
    k_gemm<FIN><<<(NNODE + 127) / 128, 128>>>(x, W1, dH);
    k_agg64f<<<gW, TB>>>(dH, b1, Ws1, nullptr, dh, ds0, nullptr);
    k_gate<<<gW8, TB>>>(ds0, dh, bs1, dx1);

    // layer 2 (fused dot with W3 for layer 3)
    k_gemm<D><<<(NNODE + 127) / 128, 128>>>(dh, W2, dH);
    k_agg64f<<<gW, TB>>>(dH, b2, Ws2, W3, dh, ds0, du);
    k_gate2<<<gW8, TB>>>(ds0, du, dh, bs2, b3, dx2);

    // layer 3 tail
    k_s3<<<gW8, TB>>>(Ws3, bs3);

    // head
    k_head<<<NGRAPH, 128>>>(Wc1, bc1, Wc2, bc2, Wl1, bl1, Wl2, bl2, out);

    (void)in_sizes; (void)n_in; (void)out_size;
}